// round 1
// baseline (speedup 1.0000x reference)
#include <cuda_runtime.h>
#include <math.h>

#define BB   2
#define CIN  16
#define CG   16      // channels per gate
#define NG   6
#define TT   31
#define HH   128
#define WW   128
#define HWSZ (HH*WW)
#define KV   27

#define TW 32
#define TH 8

// Scratch for activated gates: [gate][b][c][t][h][w]  (390 MB)
__device__ float g_gates[(size_t)NG * BB * CG * TT * HWSZ];

__global__ __launch_bounds__(256)
void conv_gates_kernel(const float* __restrict__ x,
                       const float* __restrict__ cw,
                       const float* __restrict__ cb)
{
    // weights for this gate: [(ci*27 + j)*16 + oc]  -> float4 over oc
    __shared__ float w_s[CIN * KV * CG];          // 27648 B
    __shared__ float xs[3][TH + 2][TW + 2];       // 4080 B

    const int tx  = threadIdx.x;
    const int ty  = threadIdx.y;
    const int tid = ty * TW + tx;
    const int w0  = blockIdx.x * TW;
    const int h0  = blockIdx.y * TH;
    int z = blockIdx.z;
    const int t = z % TT; z /= TT;
    const int g = z % NG;
    const int b = z / NG;

    // stage weights for this gate's 16 output channels
    for (int i = tid; i < CIN * KV * CG; i += 256) {
        int oc = i & 15;
        int cj = i >> 4;                 // ci*27 + j
        w_s[i] = cw[(g * CG + oc) * (CIN * KV) + cj];
    }

    float acc[CG];
#pragma unroll
    for (int oc = 0; oc < CG; oc++)
        acc[oc] = __ldg(&cb[g * CG + oc]);

    const float* xbase = x + (size_t)b * CIN * TT * HWSZ;

    for (int ci = 0; ci < CIN; ci++) {
        __syncthreads();   // protect previous iter's xs reads; fences w_s on iter 0
        // load x slice [3 t][TH+2][TW+2] with zero padding
        const float* xb = xbase + (size_t)ci * TT * HWSZ;
        for (int i = tid; i < 3 * (TH + 2) * (TW + 2); i += 256) {
            int dt  = i / ((TH + 2) * (TW + 2));
            int rem = i % ((TH + 2) * (TW + 2));
            int ih  = rem / (TW + 2);
            int iw  = rem % (TW + 2);
            int tg  = t - 1 + dt;
            int hh  = h0 - 1 + ih;
            int ww  = w0 - 1 + iw;
            float v = 0.0f;
            if (tg >= 0 && tg < TT && hh >= 0 && hh < HH && ww >= 0 && ww < WW)
                v = xb[(size_t)tg * HWSZ + hh * WW + ww];
            ((float*)xs)[i] = v;
        }
        __syncthreads();

        // gather this thread's 3x3x3 patch into registers
        float xp[KV];
#pragma unroll
        for (int dt = 0; dt < 3; dt++)
#pragma unroll
            for (int dh = 0; dh < 3; dh++)
#pragma unroll
                for (int dw = 0; dw < 3; dw++)
                    xp[dt * 9 + dh * 3 + dw] = xs[dt][ty + dh][tx + dw];

        const float4* ws4 = (const float4*)(w_s + ci * KV * CG);
#pragma unroll
        for (int j = 0; j < KV; j++) {
            float xv = xp[j];
#pragma unroll
            for (int q = 0; q < 4; q++) {
                float4 wv = ws4[j * 4 + q];
                acc[q * 4 + 0] += xv * wv.x;
                acc[q * 4 + 1] += xv * wv.y;
                acc[q * 4 + 2] += xv * wv.z;
                acc[q * 4 + 3] += xv * wv.w;
            }
        }
    }

    // activation + store
    const int hw = (h0 + ty) * WW + (w0 + tx);
    const bool use_tanh = (g == 0) || (g == 5);   // Wx, X -> tanh; others -> sigmoid
#pragma unroll
    for (int oc = 0; oc < CG; oc++) {
        float v = acc[oc];
        v = use_tanh ? tanhf(v) : (1.0f / (1.0f + expf(-v)));
        g_gates[((((size_t)g * BB + b) * CG + oc) * TT + t) * HWSZ + hw] = v;
    }
}

__global__ __launch_bounds__(256)
void sru_scan_kernel(float* __restrict__ out)
{
    const int tid = blockIdx.x * blockDim.x + threadIdx.x;   // over B*CG*HW
    const int hw = tid & (HWSZ - 1);
    const int bc = tid >> 14;        // HWSZ = 16384 = 2^14
    const int c  = bc & 15;
    const int b  = bc >> 4;

    const size_t GSZ  = (size_t)BB * CG * TT * HWSZ;
    const size_t base = (((size_t)b * CG + c) * TT) * HWSZ + hw;

    const float* WX  = g_gates + 0 * GSZ + base;
    const float* FT  = g_gates + 1 * GSZ + base;
    const float* FT2 = g_gates + 2 * GSZ + base;
    const float* RT  = g_gates + 3 * GSZ + base;
    const float* RT2 = g_gates + 4 * GSZ + base;
    const float* XX  = g_gates + 5 * GSZ + base;
    float* o = out + base;

    float htl[TT];
    // forward pass (ft, rt):  C0 = 1 - f0
    {
        float f = FT[0];
        float C = 1.0f - f;
        float r = RT[0];
        htl[0] = r * C + (1.0f - r) * XX[0];
#pragma unroll
        for (int t = 1; t < TT; t++) {
            size_t idx = (size_t)t * HWSZ;
            f = FT[idx];
            C = f * C + (1.0f - f) * WX[idx];
            float r2 = RT[idx];
            htl[t] = r2 * C + (1.0f - r2) * XX[idx];
        }
    }
    // backward pass (ft2, rt2), fused add + store
    {
        size_t idx = (size_t)(TT - 1) * HWSZ;
        float f = FT2[idx];
        float C = 1.0f - f;
        float r = RT2[idx];
        o[idx] = htl[TT - 1] + r * C + (1.0f - r) * XX[idx];
#pragma unroll
        for (int t = TT - 2; t >= 0; t--) {
            idx = (size_t)t * HWSZ;
            f = FT2[idx];
            C = f * C + (1.0f - f) * WX[idx];
            float r2 = RT2[idx];
            o[idx] = htl[t] + r2 * C + (1.0f - r2) * XX[idx];
        }
    }
}

extern "C" void kernel_launch(void* const* d_in, const int* in_sizes, int n_in,
                              void* d_out, int out_size)
{
    const float* x  = (const float*)d_in[0];   // [2,16,31,128,128]
    const float* cw = (const float*)d_in[1];   // [96,16,3,3,3]
    const float* cb = (const float*)d_in[2];   // [96]
    float* out = (float*)d_out;                // [2,16,31,128,128]

    dim3 blk(TW, TH, 1);
    dim3 grd(WW / TW, HH / TH, BB * NG * TT);
    conv_gates_kernel<<<grd, blk>>>(x, cw, cb);

    int n = BB * CG * HWSZ;                    // 524288 threads
    sru_scan_kernel<<<n / 256, 256>>>(out);
}

// round 2
// speedup vs baseline: 1.2661x; 1.2661x over previous
#include <cuda_runtime.h>
#include <math.h>

#define BB   2
#define CIN  16
#define CG   16      // channels per gate
#define NG   6
#define TT   31
#define HH   128
#define WW   128
#define HWSZ (HH*WW)
#define KV   27

// each thread computes 2 adjacent-w pixels; block covers 32w x 16h
#define TX   16      // threads in x (w-pairs)
#define TY   16      // threads in y (h)
#define BW   (TX*2)  // 32
#define BH   TY      // 16

// Scratch for activated gates: [gate][b][c][t][h][w]  (390 MB)
__device__ float g_gates[(size_t)NG * BB * CG * TT * HWSZ];

__device__ __forceinline__ void fma2(unsigned long long& d,
                                     unsigned long long a,
                                     unsigned long long b)
{
    asm("fma.rn.f32x2 %0, %1, %2, %0;" : "+l"(d) : "l"(a), "l"(b));
}

__device__ __forceinline__ unsigned long long pack2(float lo, float hi)
{
    unsigned long long r;
    asm("mov.b64 %0, {%1, %2};" : "=l"(r) : "f"(lo), "f"(hi));
    return r;
}

__device__ __forceinline__ unsigned long long dup2(float v)
{
    unsigned long long r;
    asm("mov.b64 %0, {%1, %1};" : "=l"(r) : "f"(v));
    return r;
}

__device__ __forceinline__ void unpack2(unsigned long long p, float& lo, float& hi)
{
    asm("mov.b64 {%0, %1}, %2;" : "=f"(lo), "=f"(hi) : "l"(p));
}

__global__ __launch_bounds__(256, 2)
void conv_gates_kernel(const float* __restrict__ x,
                       const float* __restrict__ cw,
                       const float* __restrict__ cb)
{
    // weights for this gate: [(ci*27 + j)*16 + oc]; oc-pairs are contiguous 8B
    __shared__ __align__(16) float w_s[CIN * KV * CG];       // 27648 B
    __shared__ float xs[3][BH + 2][BW + 2];                  // 3*18*34*4 = 7344 B

    const int tx  = threadIdx.x;                 // 0..15  (w-pair)
    const int ty  = threadIdx.y;                 // 0..15  (h)
    const int tid = ty * TX + tx;
    const int w0  = blockIdx.x * BW;
    const int h0  = blockIdx.y * BH;
    int z = blockIdx.z;
    const int t = z % TT; z /= TT;
    const int g = z % NG;
    const int b = z / NG;

    // stage weights for this gate's 16 output channels
    for (int i = tid; i < CIN * KV * CG; i += 256) {
        int oc = i & 15;
        int cj = i >> 4;                 // ci*27 + j
        w_s[i] = cw[(g * CG + oc) * (CIN * KV) + cj];
    }

    // accumulators: 8 oc-pairs per pixel, 2 pixels
    unsigned long long acc0[8], acc1[8];
#pragma unroll
    for (int q = 0; q < 8; q++) {
        unsigned long long bp = pack2(__ldg(&cb[g * CG + 2 * q]),
                                      __ldg(&cb[g * CG + 2 * q + 1]));
        acc0[q] = bp;
        acc1[q] = bp;
    }

    const float* xbase = x + (size_t)b * CIN * TT * HWSZ;

    for (int ci = 0; ci < CIN; ci++) {
        __syncthreads();   // protect previous iter's xs reads; fences w_s on iter 0
        // load x slice [3 t][BH+2][BW+2] with zero padding
        const float* xb = xbase + (size_t)ci * TT * HWSZ;
        for (int i = tid; i < 3 * (BH + 2) * (BW + 2); i += 256) {
            int dt  = i / ((BH + 2) * (BW + 2));
            int rem = i % ((BH + 2) * (BW + 2));
            int ih  = rem / (BW + 2);
            int iw  = rem % (BW + 2);
            int tg  = t - 1 + dt;
            int hh  = h0 - 1 + ih;
            int ww  = w0 - 1 + iw;
            float v = 0.0f;
            if (tg >= 0 && tg < TT && hh >= 0 && hh < HH && ww >= 0 && ww < WW)
                v = xb[(size_t)tg * HWSZ + hh * WW + ww];
            ((float*)xs)[i] = v;
        }
        __syncthreads();

        // union patch for the 2 adjacent-w pixels: [3][3][4]
        float xu[3][3][4];
#pragma unroll
        for (int dt = 0; dt < 3; dt++)
#pragma unroll
            for (int dh = 0; dh < 3; dh++)
#pragma unroll
                for (int dw = 0; dw < 4; dw++)
                    xu[dt][dh][dw] = xs[dt][ty + dh][2 * tx + dw];

#pragma unroll
        for (int dt = 0; dt < 3; dt++)
#pragma unroll
            for (int dh = 0; dh < 3; dh++)
#pragma unroll
                for (int dw = 0; dw < 3; dw++) {
                    const int j = (dt * 3 + dh) * 3 + dw;
                    unsigned long long xx0 = dup2(xu[dt][dh][dw]);
                    unsigned long long xx1 = dup2(xu[dt][dh][dw + 1]);
                    const ulonglong2* wq =
                        (const ulonglong2*)(w_s + (ci * KV + j) * CG);
#pragma unroll
                    for (int q = 0; q < 4; q++) {
                        ulonglong2 wv = wq[q];
                        fma2(acc0[2 * q],     xx0, wv.x);
                        fma2(acc0[2 * q + 1], xx0, wv.y);
                        fma2(acc1[2 * q],     xx1, wv.x);
                        fma2(acc1[2 * q + 1], xx1, wv.y);
                    }
                }
    }

    // activation + store (float2 per oc: the 2 adjacent-w pixels)
    const int hw = (h0 + ty) * WW + (w0 + 2 * tx);
    const bool use_tanh = (g == 0) || (g == 5);   // Wx, X -> tanh; others -> sigmoid
    float* gb = g_gates + (((size_t)g * BB + b) * CG * TT) * HWSZ + (size_t)t * HWSZ + hw;
#pragma unroll
    for (int q = 0; q < 8; q++) {
        float a0, a1, b0, b1;
        unpack2(acc0[q], a0, b0);   // oc=2q: pixel0 in lo? no: acc0 holds pixel0's pair
        unpack2(acc1[q], a1, b1);
        // acc0[q] = {oc=2q px0, oc=2q+1 px0}; acc1[q] = {oc=2q px1, oc=2q+1 px1}
        float v00 = a0, v10 = b0;   // pixel0: oc 2q, 2q+1
        float v01 = a1, v11 = b1;   // pixel1: oc 2q, 2q+1
        if (use_tanh) {
            v00 = tanhf(v00); v10 = tanhf(v10);
            v01 = tanhf(v01); v11 = tanhf(v11);
        } else {
            v00 = 1.0f / (1.0f + expf(-v00)); v10 = 1.0f / (1.0f + expf(-v10));
            v01 = 1.0f / (1.0f + expf(-v01)); v11 = 1.0f / (1.0f + expf(-v11));
        }
        // oc = 2q
        *(float2*)(gb + (size_t)(2 * q) * TT * HWSZ)     = make_float2(v00, v01);
        // oc = 2q+1
        *(float2*)(gb + (size_t)(2 * q + 1) * TT * HWSZ) = make_float2(v10, v11);
    }
}

__global__ __launch_bounds__(256)
void sru_scan_kernel(float* __restrict__ out)
{
    const int tid = blockIdx.x * blockDim.x + threadIdx.x;   // over B*CG*HW
    const int hw = tid & (HWSZ - 1);
    const int bc = tid >> 14;        // HWSZ = 16384 = 2^14
    const int c  = bc & 15;
    const int b  = bc >> 4;

    const size_t GSZ  = (size_t)BB * CG * TT * HWSZ;
    const size_t base = (((size_t)b * CG + c) * TT) * HWSZ + hw;

    const float* WX  = g_gates + 0 * GSZ + base;
    const float* FT  = g_gates + 1 * GSZ + base;
    const float* FT2 = g_gates + 2 * GSZ + base;
    const float* RT  = g_gates + 3 * GSZ + base;
    const float* RT2 = g_gates + 4 * GSZ + base;
    const float* XX  = g_gates + 5 * GSZ + base;
    float* o = out + base;

    float htl[TT];
    // forward pass (ft, rt):  C0 = 1 - f0
    {
        float f = FT[0];
        float C = 1.0f - f;
        float r = RT[0];
        htl[0] = r * C + (1.0f - r) * XX[0];
#pragma unroll
        for (int t = 1; t < TT; t++) {
            size_t idx = (size_t)t * HWSZ;
            f = FT[idx];
            C = f * C + (1.0f - f) * WX[idx];
            float r2 = RT[idx];
            htl[t] = r2 * C + (1.0f - r2) * XX[idx];
        }
    }
    // backward pass (ft2, rt2), fused add + store
    {
        size_t idx = (size_t)(TT - 1) * HWSZ;
        float f = FT2[idx];
        float C = 1.0f - f;
        float r = RT2[idx];
        o[idx] = htl[TT - 1] + r * C + (1.0f - r) * XX[idx];
#pragma unroll
        for (int t = TT - 2; t >= 0; t--) {
            idx = (size_t)t * HWSZ;
            f = FT2[idx];
            C = f * C + (1.0f - f) * WX[idx];
            float r2 = RT2[idx];
            o[idx] = htl[t] + r2 * C + (1.0f - r2) * XX[idx];
        }
    }
}

extern "C" void kernel_launch(void* const* d_in, const int* in_sizes, int n_in,
                              void* d_out, int out_size)
{
    const float* x  = (const float*)d_in[0];   // [2,16,31,128,128]
    const float* cw = (const float*)d_in[1];   // [96,16,3,3,3]
    const float* cb = (const float*)d_in[2];   // [96]
    float* out = (float*)d_out;                // [2,16,31,128,128]

    dim3 blk(TX, TY, 1);
    dim3 grd(WW / BW, HH / BH, BB * NG * TT);
    conv_gates_kernel<<<grd, blk>>>(x, cw, cb);

    int n = BB * CG * HWSZ;                    // 524288 threads
    sru_scan_kernel<<<n / 256, 256>>>(out);
}